// round 9
// baseline (speedup 1.0000x reference)
#include <cuda_runtime.h>
#include <cuda_bf16.h>
#include <cstdint>

#define D_OUT 32768
#define D_IN  1024
#define MT 128            // rows per CTA
#define NTC 128           // sigma-rows (n) per chunk
#define NCH 8             // D_IN / NTC
#define KS 64             // k per SMEM stage
#define KSTEPS 16         // D_IN / KS
#define NCTA 256          // D_OUT / MT
#define THREADS 256
#define PREP_BLOCKS 2048
#define PREP_THREADS 256

// SMEM: stage0 A@0 B@16384, stage1 A@32768 B@49152, red arrays @65536
#define STG_A0 0
#define STG_B0 16384
#define STG_STRIDE 32768
#define RED_OFF 65536
#define SMEM_BYTES (RED_OFF + 256 * 4)   // 66560

// ---------------- device scratch (no allocations allowed) ----------------
__device__ __align__(16) __nv_bfloat16 g_Db[33554432];   // D in bf16 [32768 x 1024]
__device__ __align__(16) __nv_bfloat16 g_Sb[1048576];    // Sigma in bf16 [1024 x 1024] row-major
__device__ float g_bin[PREP_BLOCKS];
__device__ float g_act[NCTA];
__device__ float g_geom[NCTA];

// ---------------- portable PTX helpers (NO tcgen05 / no 'a' features) ----------------
__device__ __forceinline__ uint32_t smem_u32(const void* p) {
    uint32_t a;
    asm("{ .reg .u64 t; cvta.to.shared.u64 t, %1; cvt.u32.u64 %0, t; }" : "=r"(a) : "l"(p));
    return a;
}
__device__ __forceinline__ void cp_async16(uint32_t dst, const void* src) {
    asm volatile("cp.async.cg.shared.global [%0], [%1], 16;" :: "r"(dst), "l"(src) : "memory");
}
#define CP_COMMIT() asm volatile("cp.async.commit_group;" ::: "memory")
#define CP_WAIT(n)  asm volatile("cp.async.wait_group %0;" :: "n"(n) : "memory")

__device__ __forceinline__ void ldsm4(uint32_t* r, uint32_t addr) {
    asm volatile("ldmatrix.sync.aligned.m8n8.x4.shared.b16 {%0,%1,%2,%3}, [%4];"
                 : "=r"(r[0]), "=r"(r[1]), "=r"(r[2]), "=r"(r[3]) : "r"(addr));
}
__device__ __forceinline__ void mma16816(float* c, const uint32_t* a, const uint32_t* b) {
    asm volatile(
        "mma.sync.aligned.m16n8k16.row.col.f32.bf16.bf16.f32 "
        "{%0,%1,%2,%3}, {%4,%5,%6,%7}, {%8,%9}, {%0,%1,%2,%3};"
        : "+f"(c[0]), "+f"(c[1]), "+f"(c[2]), "+f"(c[3])
        : "r"(a[0]), "r"(a[1]), "r"(a[2]), "r"(a[3]), "r"(b[0]), "r"(b[1]));
}
__device__ __forceinline__ uint32_t swz(uint32_t off) { return off ^ ((off >> 3) & 0x70); }

// ---------------- kernel 1: Sigma f32 -> bf16 (no transpose needed) ----------------
__global__ void k_sigma(const float4* __restrict__ S4) {
    unsigned i = blockIdx.x * 256 + threadIdx.x;    // 262144 float4s, 1024 blocks
    float4 v = S4[i];
    __nv_bfloat162* o = reinterpret_cast<__nv_bfloat162*>(g_Sb);
    o[2 * i]     = __floats2bfloat162_rn(v.x, v.y);
    o[2 * i + 1] = __floats2bfloat162_rn(v.z, v.w);
}

// ---------------- kernel 2: prep (Th, D=W-s(Q+Th) in bf16, binary reg) ----------------
__global__ void __launch_bounds__(PREP_THREADS) k_prep(
    const float4* __restrict__ W4, const float4* __restrict__ Q4,
    const float* __restrict__ s, const float4* __restrict__ T4)
{
    __shared__ float red[PREP_THREADS];
    const unsigned n4 = 33554432u / 4u;
    float bin = 0.f;
    __nv_bfloat162* Db2 = reinterpret_cast<__nv_bfloat162*>(g_Db);
    for (unsigned i = blockIdx.x * blockDim.x + threadIdx.x; i < n4; i += gridDim.x * blockDim.x) {
        int row = (int)(i >> 8);
        float sv = s[row];
        float4 w = W4[i], q = Q4[i], t = T4[i];
        float th0 = fminf(fmaxf(0.6f * tanhf(t.x) + 0.5f, 0.f), 1.f);
        float th1 = fminf(fmaxf(0.6f * tanhf(t.y) + 0.5f, 0.f), 1.f);
        float th2 = fminf(fmaxf(0.6f * tanhf(t.z) + 0.5f, 0.f), 1.f);
        float th3 = fminf(fmaxf(0.6f * tanhf(t.w) + 0.5f, 0.f), 1.f);
        float d0 = w.x - sv * (q.x + th0);
        float d1 = w.y - sv * (q.y + th1);
        float d2 = w.z - sv * (q.z + th2);
        float d3 = w.w - sv * (q.w + th3);
        Db2[2 * i]     = __floats2bfloat162_rn(d0, d1);
        Db2[2 * i + 1] = __floats2bfloat162_rn(d2, d3);
        float u0 = 2.f * th0 - 1.f, u1 = 2.f * th1 - 1.f;
        float u2 = 2.f * th2 - 1.f, u3 = 2.f * th3 - 1.f;
        bin += (1.f - u0 * u0) + (1.f - u1 * u1) + (1.f - u2 * u2) + (1.f - u3 * u3);
    }
    red[threadIdx.x] = bin;
    __syncthreads();
    for (int o = PREP_THREADS / 2; o > 0; o >>= 1) {
        if (threadIdx.x < o) red[threadIdx.x] += red[threadIdx.x + o];
        __syncthreads();
    }
    if (threadIdx.x == 0) g_bin[blockIdx.x] = red[0];
}

// ---------------- kernel 3: Y = D @ Sigma^T via mma.sync, fused rowwise dots ----------------
// Y[i][j] = sum_k D[i,k] * Sigma[j,k]  (B = Sigma row-major, K-contiguous -> .row.col mma)
// a_i = dot(W_row_i, Y_row_i) -> geom;  r_i = dot(D_row_i, Y_row_i) -> act
__global__ void __launch_bounds__(THREADS, 2) k_main(const float* __restrict__ W) {
    extern __shared__ __align__(16) char smem[];
    uint32_t sb = smem_u32(smem);
    int tid = threadIdx.x, lane = tid & 31, wid = tid >> 5;
    int warpM = wid & 3, warpN = wid >> 2;     // 4 x 2 warp grid: 32m x 64n per warp
    int rowBase = blockIdx.x * MT;

    const uint4* gA = reinterpret_cast<const uint4*>(g_Db) + (size_t)rowBase * (D_IN / 8);
    const uint4* gB = reinterpret_cast<const uint4*>(g_Sb);

    // ldmatrix per-lane address components
    int aRow = (lane & 7) + ((lane >> 3) & 1) * 8;   // A: m within 16-tile
    int aKb  = ((lane >> 4) & 1) * 16;               // A: k-byte half
    int bRow = (lane & 7) + ((lane >> 4) & 1) * 8;   // B: n within 16-tile
    int bKb  = ((lane >> 3) & 1) * 16;               // B: k-byte half

    float pa[4] = {0.f, 0.f, 0.f, 0.f};   // running w.y dots (4 rows/thread)
    float ra[4] = {0.f, 0.f, 0.f, 0.f};   // running d.y dots

    for (int nc = 0; nc < NCH; ++nc) {
        const uint4* gBn = gB + (size_t)(nc * NTC) * (D_IN / 8);

        float acc[2][8][4];
        #pragma unroll
        for (int mi = 0; mi < 2; ++mi)
            #pragma unroll
            for (int ni = 0; ni < 8; ++ni)
                #pragma unroll
                for (int e = 0; e < 4; ++e) acc[mi][ni][e] = 0.f;

        // prologue: stage 0
        {
            uint32_t sA = sb + STG_A0, sB = sb + STG_B0;
            #pragma unroll
            for (int it = 0; it < 4; ++it) {
                int u = tid + it * THREADS;      // 0..1023
                int r = u >> 3, k8 = u & 7;
                uint32_t so = swz((uint32_t)((r << 7) | (k8 << 4)));
                cp_async16(sA + so, gA  + (size_t)r * 128 + k8);
                cp_async16(sB + so, gBn + (size_t)r * 128 + k8);
            }
            CP_COMMIT();
        }

        for (int ks = 0; ks < KSTEPS; ++ks) {
            int cur = ks & 1;
            if (ks + 1 < KSTEPS) {
                int nxt = (ks + 1) & 1;
                uint32_t sA = sb + STG_A0 + nxt * STG_STRIDE;
                uint32_t sB = sb + STG_B0 + nxt * STG_STRIDE;
                int kc = (ks + 1) * 8;
                #pragma unroll
                for (int it = 0; it < 4; ++it) {
                    int u = tid + it * THREADS;
                    int r = u >> 3, k8 = u & 7;
                    uint32_t so = swz((uint32_t)((r << 7) | (k8 << 4)));
                    cp_async16(sA + so, gA  + (size_t)r * 128 + kc + k8);
                    cp_async16(sB + so, gBn + (size_t)r * 128 + kc + k8);
                }
                CP_COMMIT();
                CP_WAIT(1);
            } else {
                CP_WAIT(0);
            }
            __syncthreads();

            uint32_t sA = sb + STG_A0 + cur * STG_STRIDE;
            uint32_t sB = sb + STG_B0 + cur * STG_STRIDE;
            #pragma unroll
            for (int kk = 0; kk < 4; ++kk) {
                uint32_t afr[2][4], bfr[4][4];
                #pragma unroll
                for (int mi = 0; mi < 2; ++mi) {
                    uint32_t off = (uint32_t)((warpM * 32 + mi * 16 + aRow) * 128 + kk * 32 + aKb);
                    ldsm4(afr[mi], sA + swz(off));
                }
                #pragma unroll
                for (int n2 = 0; n2 < 4; ++n2) {
                    uint32_t off = (uint32_t)((warpN * 64 + n2 * 16 + bRow) * 128 + kk * 32 + bKb);
                    ldsm4(bfr[n2], sB + swz(off));
                }
                #pragma unroll
                for (int mi = 0; mi < 2; ++mi)
                    #pragma unroll
                    for (int ni = 0; ni < 8; ++ni)
                        mma16816(acc[mi][ni], afr[mi], &bfr[ni >> 1][(ni & 1) * 2]);
            }
            __syncthreads();
        }

        // fold accumulators into per-row running dots (chunk cols nc*128 .. +127)
        int colBase = nc * NTC + warpN * 64;
        #pragma unroll
        for (int mi = 0; mi < 2; ++mi) {
            #pragma unroll
            for (int h = 0; h < 2; ++h) {
                int row = rowBase + warpM * 32 + mi * 16 + (lane >> 2) + h * 8;
                const float2* w2 = reinterpret_cast<const float2*>(W + (size_t)row * D_IN);
                const __nv_bfloat162* d2 = reinterpret_cast<const __nv_bfloat162*>(g_Db) + (size_t)row * (D_IN / 2);
                float accP = 0.f, accR = 0.f;
                #pragma unroll
                for (int ni = 0; ni < 8; ++ni) {
                    int cp = (colBase + ni * 8) / 2 + (lane & 3);
                    float2 wv = w2[cp];
                    float2 dv = __bfloat1622float2(d2[cp]);
                    float y0 = acc[mi][ni][h * 2], y1 = acc[mi][ni][h * 2 + 1];
                    accP = fmaf(wv.x, y0, fmaf(wv.y, y1, accP));
                    accR = fmaf(dv.x, y0, fmaf(dv.y, y1, accR));
                }
                pa[mi * 2 + h] += accP;
                ra[mi * 2 + h] += accR;
            }
        }
    }

    // deterministic reduction: quad lanes hold col-partials of the same row
    #pragma unroll
    for (int m = 0; m < 4; ++m) {
        pa[m] += __shfl_xor_sync(0xffffffffu, pa[m], 1);
        pa[m] += __shfl_xor_sync(0xffffffffu, pa[m], 2);
        ra[m] += __shfl_xor_sync(0xffffffffu, ra[m], 1);
        ra[m] += __shfl_xor_sync(0xffffffffu, ra[m], 2);
    }
    float* sW = reinterpret_cast<float*>(smem + RED_OFF);   // per-row a_i
    float* sD = sW + 128;                                   // per-row r_i
    if (warpN == 0 && (lane & 3) == 0) {
        #pragma unroll
        for (int m = 0; m < 4; ++m) {
            int rl = warpM * 32 + (m >> 1) * 16 + (lane >> 2) + (m & 1) * 8;
            sW[rl] = pa[m];
            sD[rl] = ra[m];
        }
    }
    __syncthreads();
    if (warpN == 1 && (lane & 3) == 0) {
        #pragma unroll
        for (int m = 0; m < 4; ++m) {
            int rl = warpM * 32 + (m >> 1) * 16 + (lane >> 2) + (m & 1) * 8;
            sW[rl] += pa[m];
            sD[rl] += ra[m];
        }
    }
    __syncthreads();
    if (tid < 128) {
        float ai = sW[tid];
        sW[tid] = 4.f * ai * ai;   // geom per row
    }
    __syncthreads();
    for (int o = 64; o > 0; o >>= 1) {
        if (tid < o) { sW[tid] += sW[tid + o]; sD[tid] += sD[tid + o]; }
        __syncthreads();
    }
    if (tid == 0) {
        g_geom[blockIdx.x] = sW[0];
        g_act[blockIdx.x]  = sD[0];
    }
}

// ---------------- kernel 4: final deterministic combine ----------------
__global__ void k_final(float* __restrict__ out) {
    __shared__ float red[256];
    int tid = threadIdx.x;
    float b = 0.f, a = 0.f, g = 0.f;
    for (int i = tid; i < PREP_BLOCKS; i += 256) b += g_bin[i];
    for (int i = tid; i < NCTA; i += 256) { a += g_act[i]; g += g_geom[i]; }
    float v = a + 2.0e-4f * b + 0.05f * g;
    red[tid] = v;
    __syncthreads();
    for (int o = 128; o > 0; o >>= 1) {
        if (tid < o) red[tid] += red[tid + o];
        __syncthreads();
    }
    if (tid == 0) out[0] = red[0];
}

// ---------------- launch ----------------
extern "C" void kernel_launch(void* const* d_in, const int* in_sizes, int n_in,
                              void* d_out, int out_size) {
    const float* W     = (const float*)d_in[0];
    const float* Sigma = (const float*)d_in[1];
    const float* Q     = (const float*)d_in[2];
    const float* s     = (const float*)d_in[3];
    const float* Theta = (const float*)d_in[4];
    float* out = (float*)d_out;

    cudaFuncSetAttribute(k_main, cudaFuncAttributeMaxDynamicSharedMemorySize, SMEM_BYTES);

    k_sigma<<<1024, 256>>>((const float4*)Sigma);
    k_prep<<<PREP_BLOCKS, PREP_THREADS>>>(
        (const float4*)W, (const float4*)Q, s, (const float4*)Theta);
    k_main<<<NCTA, THREADS, SMEM_BYTES>>>(W);
    k_final<<<1, 256>>>(out);
}